// round 7
// baseline (speedup 1.0000x reference)
#include <cuda_runtime.h>
#include <cuda_bf16.h>
#include <cstdint>

// Problem constants
#define D1_  270
#define K_   32
#define C_   60
#define B_   64
#define T_   4096
#define P_   (K_*K_)          // 1024

// ---------------- device scratch (no allocation allowed) ----------------
__device__ float g_ct[P_ * C_];     // cos(phase)[p][c]
__device__ float g_st[P_ * C_];     // sin(phase)[p][c]
__device__ float g_w [D1_ * C_];    // softmax weights [j][c]

// ---------------- kernel 1: trig tables (double-precision phase; proven) ----
__global__ void trig_kernel(const float* __restrict__ loc) {
    int i = blockIdx.x * 256 + threadIdx.x;
    if (i >= P_ * C_) return;
    int p = i / C_, c = i - p * C_;
    int k = p >> 5, l = p & 31;
    double x = (double)loc[2 * c];
    double y = (double)loc[2 * c + 1];
    double ph = 6.283185307179586476925286766559 * ((double)k * x + (double)l * y);
    double s, co;
    sincos(ph, &s, &co);
    g_ct[i] = (float)co;
    g_st[i] = (float)s;
}

// ---------------- kernel 2: weights + softmax (6 j per block) ----------------
#define JB 6
__global__ void weights_kernel(const float* __restrict__ zre,
                               const float* __restrict__ zim) {
    int jb = blockIdx.x * JB;
    int tid = threadIdx.x;
    int s = tid >> 6, c = tid & 63;

    float acc[JB];
    #pragma unroll
    for (int u = 0; u < JB; u++) acc[u] = 0.f;

    if (c < C_) {
        int p0 = s * 256;
        for (int p = p0; p < p0 + 256; p++) {
            float ct = g_ct[p * C_ + c];
            float st = g_st[p * C_ + c];
            #pragma unroll
            for (int u = 0; u < JB; u++) {
                acc[u] += zre[(jb + u) * P_ + p] * ct + zim[(jb + u) * P_ + p] * st;
            }
        }
    }

    __shared__ float part[JB][4][64];
    __shared__ float ex[JB][64];
    __shared__ float tot[JB];
    #pragma unroll
    for (int u = 0; u < JB; u++) part[u][s][c] = acc[u];
    __syncthreads();
    if (s == 0 && c < C_) {
        #pragma unroll
        for (int u = 0; u < JB; u++) {
            float a = part[u][0][c] + part[u][1][c] + part[u][2][c] + part[u][3][c];
            ex[u][c] = expf(a);
        }
    }
    __syncthreads();
    if (tid < JB) {
        float t = 0.f;
        #pragma unroll
        for (int i = 0; i < C_; i++) t += ex[tid][i];
        tot[tid] = t;
    }
    __syncthreads();
    if (s == 0 && c < C_) {
        #pragma unroll
        for (int u = 0; u < JB; u++) g_w[(jb + u) * C_ + c] = ex[u][c] / tot[u];
    }
}

// ---------------- kernel 3: HMMA GEMM (mma.sync bf16, 3-pass hi/lo split) ---
// out[b, j0:j0+96, t0:t0+64] = W[96,60] @ X[b, 60, t0:t0+64]
// smem rows padded to 144B -> ldmatrix 8-row reads hit banks 4*r mod 32
// (conflict-free), STS.128 staging at the 4-wavefront floor.
#define ROWB 144
#define WHI  0
#define WLO  (96 * ROWB)            // 13824
#define XHI  (2 * 96 * ROWB)        // 27648
#define XLO  (2 * 96 * ROWB + 64 * ROWB)   // 36864
#define SMEMB (2 * 96 * ROWB + 2 * 64 * ROWB) // 46080

__device__ __forceinline__ uint32_t smem_u32(const void* p) {
    uint32_t a;
    asm("{ .reg .u64 t; cvta.to.shared.u64 t, %1; cvt.u32.u64 %0, t; }"
        : "=r"(a) : "l"(p));
    return a;
}

__device__ __forceinline__ void ldm_x4(uint32_t* r, uint32_t addr) {
    asm volatile("ldmatrix.sync.aligned.m8n8.x4.shared.b16 {%0,%1,%2,%3}, [%4];"
                 : "=r"(r[0]), "=r"(r[1]), "=r"(r[2]), "=r"(r[3]) : "r"(addr));
}

__device__ __forceinline__ void mma_bf16(float* d, const uint32_t* a, const uint32_t* b) {
    asm volatile(
        "mma.sync.aligned.m16n8k16.row.col.f32.bf16.bf16.f32 "
        "{%0,%1,%2,%3}, {%4,%5,%6,%7}, {%8,%9}, {%0,%1,%2,%3};"
        : "+f"(d[0]), "+f"(d[1]), "+f"(d[2]), "+f"(d[3])
        : "r"(a[0]), "r"(a[1]), "r"(a[2]), "r"(a[3]), "r"(b[0]), "r"(b[1]));
}

// split v into bf16 hi + bf16 lo (packed pairs)
__device__ __forceinline__ void split8(const float* v, uint32_t* hi, uint32_t* lo) {
    #pragma unroll
    for (int q = 0; q < 4; q++) {
        __nv_bfloat162 h = __floats2bfloat162_rn(v[2*q], v[2*q+1]);
        float r0 = v[2*q]   - __bfloat162float(h.x);
        float r1 = v[2*q+1] - __bfloat162float(h.y);
        __nv_bfloat162 l = __floats2bfloat162_rn(r0, r1);
        hi[q] = *(uint32_t*)&h;
        lo[q] = *(uint32_t*)&l;
    }
}

__global__ void __launch_bounds__(192)
mma_kernel(const float* __restrict__ X, float* __restrict__ out) {
    __shared__ __align__(16) char sm[SMEMB];
    uint32_t smb = smem_u32(sm);

    int tid  = threadIdx.x;
    int wid  = tid >> 5, lane = tid & 31;
    int t0   = blockIdx.x * 64;
    int j0   = blockIdx.y * 96;
    int b    = blockIdx.z;

    // ---- stage W hi/lo: tasks (j 96, c-octet 8) ----
    #pragma unroll 1
    for (int task = tid; task < 96 * 8; task += 192) {
        int j = task >> 3, oc = task & 7;
        float v[8];
        #pragma unroll
        for (int i = 0; i < 8; i++) {
            int c = oc * 8 + i;
            v[i] = (c < C_ && (j0 + j) < D1_) ? g_w[(j0 + j) * C_ + c] : 0.f;
        }
        uint32_t hi[4], lo[4];
        split8(v, hi, lo);
        *(uint4*)(sm + WHI + j * ROWB + oc * 16) = *(uint4*)hi;
        *(uint4*)(sm + WLO + j * ROWB + oc * 16) = *(uint4*)lo;
    }

    // ---- stage X hi/lo transposed: tasks (c-octet 8, t 64) ----
    const float* Xb = X + (size_t)b * C_ * T_ + t0;
    #pragma unroll 1
    for (int task = tid; task < 8 * 64; task += 192) {
        int oc = task >> 6, t = task & 63;
        float v[8];
        #pragma unroll
        for (int i = 0; i < 8; i++) {
            int c = oc * 8 + i;
            v[i] = (c < C_) ? Xb[(size_t)c * T_ + t] : 0.f;
        }
        uint32_t hi[4], lo[4];
        split8(v, hi, lo);
        *(uint4*)(sm + XHI + t * ROWB + oc * 16) = *(uint4*)hi;
        *(uint4*)(sm + XLO + t * ROWB + oc * 16) = *(uint4*)lo;
    }
    __syncthreads();

    // ---- main: warp (wj 0..2, wt 0..1) -> 32j x 32t ----
    int wj = wid >> 1, wt = wid & 1;
    int r  = lane & 7, mi = lane >> 3;

    // ldmatrix lane-address components
    int arow  = wj * 32 + (mi & 1) * 8 + r;        // + jf*16
    int acoff = (mi >> 1) * 8;                     // k sub-offset
    int brow  = wt * 32 + (mi >> 1) * 8 + r;       // + nt*16
    int bcoff = (mi & 1) * 8;

    float acc[2][4][4];
    #pragma unroll
    for (int jf = 0; jf < 2; jf++)
        #pragma unroll
        for (int nf = 0; nf < 4; nf++)
            #pragma unroll
            for (int q = 0; q < 4; q++) acc[jf][nf][q] = 0.f;

    #pragma unroll
    for (int k = 0; k < 4; k++) {
        uint32_t Ah[2][4], Al[2][4], Bh[4][2], Bl[4][2];
        #pragma unroll
        for (int jf = 0; jf < 2; jf++) {
            uint32_t off = (uint32_t)((arow + jf * 16) * ROWB + (k * 16 + acoff) * 2);
            ldm_x4(Ah[jf], smb + WHI + off);
            ldm_x4(Al[jf], smb + WLO + off);
        }
        #pragma unroll
        for (int nt = 0; nt < 2; nt++) {
            uint32_t off = (uint32_t)((brow + nt * 16) * ROWB + (k * 16 + bcoff) * 2);
            uint32_t rh[4], rl[4];
            ldm_x4(rh, smb + XHI + off);
            ldm_x4(rl, smb + XLO + off);
            Bh[2*nt][0] = rh[0]; Bh[2*nt][1] = rh[1];
            Bh[2*nt+1][0] = rh[2]; Bh[2*nt+1][1] = rh[3];
            Bl[2*nt][0] = rl[0]; Bl[2*nt][1] = rl[1];
            Bl[2*nt+1][0] = rl[2]; Bl[2*nt+1][1] = rl[3];
        }
        #pragma unroll
        for (int jf = 0; jf < 2; jf++)
            #pragma unroll
            for (int nf = 0; nf < 4; nf++) {
                mma_bf16(acc[jf][nf], Ah[jf], Bh[nf]);   // hi*hi
                mma_bf16(acc[jf][nf], Ah[jf], Bl[nf]);   // hi*lo
                mma_bf16(acc[jf][nf], Al[jf], Bh[nf]);   // lo*hi
            }
    }

    // ---- epilogue: float2 stores, predicated on j < 270 ----
    int g = lane >> 2, q2 = (lane & 3) * 2;
    #pragma unroll
    for (int jf = 0; jf < 2; jf++) {
        int j = j0 + wj * 32 + jf * 16 + g;
        #pragma unroll
        for (int nf = 0; nf < 4; nf++) {
            int t = t0 + wt * 32 + nf * 8 + q2;
            if (j < D1_) {
                float2 v0 = make_float2(acc[jf][nf][0], acc[jf][nf][1]);
                *(float2*)(out + ((size_t)b * D1_ + j) * T_ + t) = v0;
            }
            if (j + 8 < D1_) {
                float2 v1 = make_float2(acc[jf][nf][2], acc[jf][nf][3]);
                *(float2*)(out + ((size_t)b * D1_ + j + 8) * T_ + t) = v1;
            }
        }
    }
}

// ---------------- launch ----------------
extern "C" void kernel_launch(void* const* d_in, const int* in_sizes, int n_in,
                              void* d_out, int out_size) {
    const float* X   = (const float*)d_in[0];   // [64, 60, 4096]
    const float* zre = (const float*)d_in[1];   // [270, 32, 32]
    const float* zim = (const float*)d_in[2];   // [270, 32, 32]
    const float* loc = (const float*)d_in[3];   // [60, 2]
    float* out = (float*)d_out;                 // [64, 270, 4096]

    trig_kernel<<<(P_ * C_ + 255) / 256, 256>>>(loc);
    weights_kernel<<<D1_ / JB, 256>>>(zre, zim);
    dim3 grid(T_ / 64, 3, B_);   // t fastest -> X tile reused across j-blocks in L2
    mma_kernel<<<grid, 192>>>(X, out);
}

// round 8
// speedup vs baseline: 1.5836x; 1.5836x over previous
#include <cuda_runtime.h>
#include <cuda_bf16.h>
#include <cstdint>

// Problem constants
#define D1_  270
#define K_   32
#define C_   60
#define B_   64
#define T_   4096
#define P_   (K_*K_)          // 1024

// ---------------- device scratch (no allocation allowed) ----------------
__device__ float g_ct[P_ * C_];     // cos(phase)[p][c]
__device__ float g_st[P_ * C_];     // sin(phase)[p][c]
__device__ float g_w [D1_ * C_];    // softmax weights [j][c]

// pre-split bf16 operands (ldmatrix-ready layouts)
__device__ __align__(16) __nv_bfloat16 g_whi[3 * 96 * 72];      // [jb][row][c pad 72]
__device__ __align__(16) __nv_bfloat16 g_wlo[3 * 96 * 72];
__device__ __align__(16) __nv_bfloat16 g_xhi[(size_t)B_ * 64 * T_];  // [b][c pad 64][t]
__device__ __align__(16) __nv_bfloat16 g_xlo[(size_t)B_ * 64 * T_];

// ---------------- kernel 1: trig tables (double-precision phase; proven) ----
__global__ void trig_kernel(const float* __restrict__ loc) {
    int i = blockIdx.x * 256 + threadIdx.x;
    if (i >= P_ * C_) return;
    int p = i / C_, c = i - p * C_;
    int k = p >> 5, l = p & 31;
    double x = (double)loc[2 * c];
    double y = (double)loc[2 * c + 1];
    double ph = 6.283185307179586476925286766559 * ((double)k * x + (double)l * y);
    double s, co;
    sincos(ph, &s, &co);
    g_ct[i] = (float)co;
    g_st[i] = (float)s;
}

// ---------------- kernel 2: weights + softmax (6 j per block) ----------------
#define JB 6
__global__ void weights_kernel(const float* __restrict__ zre,
                               const float* __restrict__ zim) {
    int jb = blockIdx.x * JB;
    int tid = threadIdx.x;
    int s = tid >> 6, c = tid & 63;

    float acc[JB];
    #pragma unroll
    for (int u = 0; u < JB; u++) acc[u] = 0.f;

    if (c < C_) {
        int p0 = s * 256;
        for (int p = p0; p < p0 + 256; p++) {
            float ct = g_ct[p * C_ + c];
            float st = g_st[p * C_ + c];
            #pragma unroll
            for (int u = 0; u < JB; u++) {
                acc[u] += zre[(jb + u) * P_ + p] * ct + zim[(jb + u) * P_ + p] * st;
            }
        }
    }

    __shared__ float part[JB][4][64];
    __shared__ float ex[JB][64];
    __shared__ float tot[JB];
    #pragma unroll
    for (int u = 0; u < JB; u++) part[u][s][c] = acc[u];
    __syncthreads();
    if (s == 0 && c < C_) {
        #pragma unroll
        for (int u = 0; u < JB; u++) {
            float a = part[u][0][c] + part[u][1][c] + part[u][2][c] + part[u][3][c];
            ex[u][c] = expf(a);
        }
    }
    __syncthreads();
    if (tid < JB) {
        float t = 0.f;
        #pragma unroll
        for (int i = 0; i < C_; i++) t += ex[tid][i];
        tot[tid] = t;
    }
    __syncthreads();
    if (s == 0 && c < C_) {
        #pragma unroll
        for (int u = 0; u < JB; u++) g_w[(jb + u) * C_ + c] = ex[u][c] / tot[u];
    }
}

// ---------------- kernel 2b: W -> bf16 hi/lo padded tiles ----------------
__global__ void wtile_kernel() {
    int idx = blockIdx.x * 256 + threadIdx.x;
    if (idx >= 3 * 96 * 72) return;
    int c = idx % 72;
    int row = (idx / 72) % 96;
    int jb = idx / (72 * 96);
    int j = jb * 96 + row;
    float v = (j < D1_ && c < C_) ? g_w[j * C_ + c] : 0.f;
    __nv_bfloat16 h = __float2bfloat16(v);
    __nv_bfloat16 l = __float2bfloat16(v - __bfloat162float(h));
    g_whi[idx] = h;
    g_wlo[idx] = l;
}

// ---------------- kernel 2c: X -> bf16 hi/lo, c padded to 64 (zero rows) ----
__global__ void xsplit_kernel(const float* __restrict__ X) {
    int idx = blockIdx.x * 256 + threadIdx.x;   // over B*64*(T/2)
    if (idx >= B_ * 64 * (T_ / 2)) return;
    int t2 = idx % (T_ / 2);
    int cc = (idx / (T_ / 2)) % 64;
    int b  = idx / ((T_ / 2) * 64);
    float2 v = make_float2(0.f, 0.f);
    if (cc < C_) v = *(const float2*)(X + ((size_t)(b * C_ + cc)) * T_ + t2 * 2);
    __nv_bfloat162 h = __floats2bfloat162_rn(v.x, v.y);
    float r0 = v.x - __bfloat162float(h.x);
    float r1 = v.y - __bfloat162float(h.y);
    __nv_bfloat162 l = __floats2bfloat162_rn(r0, r1);
    *(uint32_t*)((char*)g_xhi + (size_t)idx * 4) = *(uint32_t*)&h;
    *(uint32_t*)((char*)g_xlo + (size_t)idx * 4) = *(uint32_t*)&l;
}

// ---------------- kernel 3: HMMA GEMM, pure-copy staging ----------------
// smem: WH[96 x 144B] WL  |  XH[64 x 144B] XL   (rows 144B -> conflict-free ldm)
#define ROWB  144
#define WHo   0
#define WLo   13824
#define XHo   27648
#define XLo   36864
#define SMEMB 46080

__device__ __forceinline__ uint32_t smem_u32(const void* p) {
    uint32_t a;
    asm("{ .reg .u64 t; cvta.to.shared.u64 t, %1; cvt.u32.u64 %0, t; }"
        : "=r"(a) : "l"(p));
    return a;
}
__device__ __forceinline__ void cpa16(uint32_t dst, const void* src) {
    asm volatile("cp.async.cg.shared.global [%0], [%1], 16;"
                 :: "r"(dst), "l"(src) : "memory");
}
__device__ __forceinline__ void ldm_x4(uint32_t* r, uint32_t addr) {
    asm volatile("ldmatrix.sync.aligned.m8n8.x4.shared.b16 {%0,%1,%2,%3}, [%4];"
                 : "=r"(r[0]), "=r"(r[1]), "=r"(r[2]), "=r"(r[3]) : "r"(addr));
}
__device__ __forceinline__ void ldm_x4t(uint32_t* r, uint32_t addr) {
    asm volatile("ldmatrix.sync.aligned.m8n8.x4.trans.shared.b16 {%0,%1,%2,%3}, [%4];"
                 : "=r"(r[0]), "=r"(r[1]), "=r"(r[2]), "=r"(r[3]) : "r"(addr));
}
__device__ __forceinline__ void mma_bf16(float* d, const uint32_t* a, const uint32_t* b) {
    asm volatile(
        "mma.sync.aligned.m16n8k16.row.col.f32.bf16.bf16.f32 "
        "{%0,%1,%2,%3}, {%4,%5,%6,%7}, {%8,%9}, {%0,%1,%2,%3};"
        : "+f"(d[0]), "+f"(d[1]), "+f"(d[2]), "+f"(d[3])
        : "r"(a[0]), "r"(a[1]), "r"(a[2]), "r"(a[3]), "r"(b[0]), "r"(b[1]));
}

__global__ void __launch_bounds__(192)
mma_kernel(float* __restrict__ out) {
    __shared__ __align__(16) char sm[SMEMB];
    uint32_t smb = smem_u32(sm);

    int tid = threadIdx.x, wid = tid >> 5, lane = tid & 31;
    int t0 = blockIdx.x * 64;
    int jb = blockIdx.y;
    int j0 = jb * 96;
    int b  = blockIdx.z;

    // ---- stage W tiles (pure copy, 864 x 16B per buffer) ----
    const char* wh = (const char*)(g_whi + jb * 96 * 72);
    const char* wl = (const char*)(g_wlo + jb * 96 * 72);
    for (int i = tid; i < 864; i += 192) {
        cpa16(smb + WHo + i * 16, wh + i * 16);
        cpa16(smb + WLo + i * 16, wl + i * 16);
    }
    // ---- stage X tiles: 64 c-rows x 128B data into 144B-pitch rows ----
    const char* xh = (const char*)(g_xhi + ((size_t)b * 64) * T_ + t0);
    const char* xl = (const char*)(g_xlo + ((size_t)b * 64) * T_ + t0);
    for (int i = tid; i < 512; i += 192) {
        int row = i >> 3, o = (i & 7) * 16;
        cpa16(smb + XHo + row * ROWB + o, xh + (size_t)row * T_ * 2 + o);
        cpa16(smb + XLo + row * ROWB + o, xl + (size_t)row * T_ * 2 + o);
    }
    asm volatile("cp.async.commit_group;" ::: "memory");
    asm volatile("cp.async.wait_group 0;" ::: "memory");
    __syncthreads();

    // ---- main: warp (wj 0..2, wt 0..1) -> 32j x 32t ----
    int wj = wid >> 1, wt = wid & 1;
    int r  = lane & 7, mi = lane >> 3;

    // A (non-trans, [j][c] rows): same as proven R7 mapping
    int arow  = wj * 32 + (mi & 1) * 8 + r;
    int acoff = (mi >> 1) * 8;
    // B (trans, [c][t] rows): matrices mi -> (c + (mi&1)*8 + r, t + (mi>>1)*8)
    int bcrow = (mi & 1) * 8 + r;
    int btoff = (wt * 32 + (mi >> 1) * 8) * 2;

    float acc[2][4][4];
    #pragma unroll
    for (int jf = 0; jf < 2; jf++)
        #pragma unroll
        for (int nf = 0; nf < 4; nf++)
            #pragma unroll
            for (int q = 0; q < 4; q++) acc[jf][nf][q] = 0.f;

    #pragma unroll
    for (int k = 0; k < 4; k++) {
        uint32_t Ah[2][4], Al[2][4], Bh[4][2], Bl[4][2];
        #pragma unroll
        for (int jf = 0; jf < 2; jf++) {
            uint32_t off = (uint32_t)((arow + jf * 16) * ROWB + (k * 16 + acoff) * 2);
            ldm_x4(Ah[jf], smb + WHo + off);
            ldm_x4(Al[jf], smb + WLo + off);
        }
        #pragma unroll
        for (int nt = 0; nt < 2; nt++) {
            uint32_t off = (uint32_t)((k * 16 + bcrow) * ROWB + btoff + nt * 32);
            uint32_t rh[4], rl[4];
            ldm_x4t(rh, smb + XHo + off);
            ldm_x4t(rl, smb + XLo + off);
            Bh[2*nt][0]   = rh[0]; Bh[2*nt][1]   = rh[1];
            Bh[2*nt+1][0] = rh[2]; Bh[2*nt+1][1] = rh[3];
            Bl[2*nt][0]   = rl[0]; Bl[2*nt][1]   = rl[1];
            Bl[2*nt+1][0] = rl[2]; Bl[2*nt+1][1] = rl[3];
        }
        #pragma unroll
        for (int jf = 0; jf < 2; jf++)
            #pragma unroll
            for (int nf = 0; nf < 4; nf++) {
                mma_bf16(acc[jf][nf], Ah[jf], Bh[nf]);   // hi*hi
                mma_bf16(acc[jf][nf], Ah[jf], Bl[nf]);   // hi*lo
                mma_bf16(acc[jf][nf], Al[jf], Bh[nf]);   // lo*hi
            }
    }

    // ---- epilogue: float2 stores, predicated on j < 270 ----
    int g = lane >> 2, q2 = (lane & 3) * 2;
    #pragma unroll
    for (int jf = 0; jf < 2; jf++) {
        int j = j0 + wj * 32 + jf * 16 + g;
        #pragma unroll
        for (int nf = 0; nf < 4; nf++) {
            int t = t0 + wt * 32 + nf * 8 + q2;
            if (j < D1_) {
                float2 v0 = make_float2(acc[jf][nf][0], acc[jf][nf][1]);
                *(float2*)(out + ((size_t)b * D1_ + j) * T_ + t) = v0;
            }
            if (j + 8 < D1_) {
                float2 v1 = make_float2(acc[jf][nf][2], acc[jf][nf][3]);
                *(float2*)(out + ((size_t)b * D1_ + j + 8) * T_ + t) = v1;
            }
        }
    }
}

// ---------------- launch ----------------
extern "C" void kernel_launch(void* const* d_in, const int* in_sizes, int n_in,
                              void* d_out, int out_size) {
    const float* X   = (const float*)d_in[0];   // [64, 60, 4096]
    const float* zre = (const float*)d_in[1];   // [270, 32, 32]
    const float* zim = (const float*)d_in[2];   // [270, 32, 32]
    const float* loc = (const float*)d_in[3];   // [60, 2]
    float* out = (float*)d_out;                 // [64, 270, 4096]

    trig_kernel<<<(P_ * C_ + 255) / 256, 256>>>(loc);
    weights_kernel<<<D1_ / JB, 256>>>(zre, zim);
    wtile_kernel<<<(3 * 96 * 72 + 255) / 256, 256>>>();
    xsplit_kernel<<<B_ * 64 * (T_ / 2) / 256, 256>>>(X);
    dim3 grid(T_ / 64, 3, B_);   // t fastest -> X[b] stays L2-resident across j-blocks
    mma_kernel<<<grid, 192>>>(out);
}